// round 4
// baseline (speedup 1.0000x reference)
#include <cuda_runtime.h>

typedef unsigned long long ull;

// ---------------- f32x2 packed helpers (Blackwell FFMA2 path) ----------------
__device__ __forceinline__ ull bcast2(float x) {
    ull d; unsigned r = __float_as_uint(x);
    asm("mov.b64 %0, {%1, %1};" : "=l"(d) : "r"(r));
    return d;
}
__device__ __forceinline__ void fma2(ull& acc, ull a, ull b) {
    asm("fma.rn.f32x2 %0, %1, %2, %0;" : "+l"(acc) : "l"(a), "l"(b));
}
__device__ __forceinline__ void mul2(ull& d, ull a) {
    asm("mul.rn.f32x2 %0, %0, %1;" : "+l"(d) : "l"(a));
}
__device__ __forceinline__ float2 unpk(ull v) {
    unsigned lo, hi;
    asm("mov.b64 {%0, %1}, %2;" : "=r"(lo), "=r"(hi) : "l"(v));
    return make_float2(__uint_as_float(lo), __uint_as_float(hi));
}

// ---------------- scratch: Q/K/V in [B,H,S,64] layout ----------------
// 64 (b*h) * 2048 * 64 floats = 33.5 MB each
__device__ float g_Q[64u * 2048u * 64u];
__device__ float g_K[64u * 2048u * 64u];
__device__ float g_V[64u * 2048u * 64u];

// =====================================================================
// Kernel 1: QKV projection.  out[m,n] = sum_k X[m,k] * W[n,k] + b[n]
// Tile 128x128, BK=16, 256 threads, 8x8 microtile via f32x2 row-pairs.
// gridDim.z = 3 selects Q/K/V.  Output scattered to [B,H,S,64].
// =====================================================================
__global__ void __launch_bounds__(256) qkv_kernel(
    const float* __restrict__ X,
    const float* __restrict__ Wq, const float* __restrict__ bq,
    const float* __restrict__ Wk, const float* __restrict__ bk,
    const float* __restrict__ Wv, const float* __restrict__ bv)
{
    __shared__ float As[16][132];   // [k][m]  (transposed tile of X)
    __shared__ float Bs[16][132];   // [k][n]  (transposed tile of W)

    const int tid = threadIdx.x;
    const int tx  = tid & 15;       // col group (0..15)
    const int ty  = tid >> 4;       // row group (0..15)
    const int m0  = blockIdx.x * 128;
    const int n0  = blockIdx.y * 128;
    const int z   = blockIdx.z;

    const float* W   = (z == 0) ? Wq : (z == 1) ? Wk : Wv;
    const float* bi  = (z == 0) ? bq : (z == 1) ? bk : bv;
    float*       Out = (z == 0) ? g_Q : (z == 1) ? g_K : g_V;

    const int lrow = tid >> 2;          // 0..63
    const int lcol = (tid & 3) * 4;     // 0,4,8,12

    ull acc[4][8];
    #pragma unroll
    for (int r = 0; r < 4; r++)
        #pragma unroll
        for (int c = 0; c < 8; c++) acc[r][c] = 0ULL;

    const float* xA0 = X + (size_t)(m0 + lrow) * 1024 + lcol;
    const float* xA1 = xA0 + (size_t)64 * 1024;
    const float* xB0 = W + (size_t)(n0 + lrow) * 1024 + lcol;
    const float* xB1 = xB0 + (size_t)64 * 1024;

    for (int k0 = 0; k0 < 1024; k0 += 16) {
        // prefetch into registers (overlaps previous tile's compute)
        float4 a0 = *(const float4*)(xA0 + k0);
        float4 a1 = *(const float4*)(xA1 + k0);
        float4 b0 = *(const float4*)(xB0 + k0);
        float4 b1 = *(const float4*)(xB1 + k0);
        __syncthreads();
        As[lcol+0][lrow] = a0.x; As[lcol+1][lrow] = a0.y;
        As[lcol+2][lrow] = a0.z; As[lcol+3][lrow] = a0.w;
        As[lcol+0][lrow+64] = a1.x; As[lcol+1][lrow+64] = a1.y;
        As[lcol+2][lrow+64] = a1.z; As[lcol+3][lrow+64] = a1.w;
        Bs[lcol+0][lrow] = b0.x; Bs[lcol+1][lrow] = b0.y;
        Bs[lcol+2][lrow] = b0.z; Bs[lcol+3][lrow] = b0.w;
        Bs[lcol+0][lrow+64] = b1.x; Bs[lcol+1][lrow+64] = b1.y;
        Bs[lcol+2][lrow+64] = b1.z; Bs[lcol+3][lrow+64] = b1.w;
        __syncthreads();

        #pragma unroll
        for (int k = 0; k < 16; k++) {
            ulonglong2 aa0 = *(const ulonglong2*)&As[k][ty*8];
            ulonglong2 aa1 = *(const ulonglong2*)&As[k][ty*8 + 4];
            float4 bb0 = *(const float4*)&Bs[k][tx*4];
            float4 bb1 = *(const float4*)&Bs[k][64 + tx*4];
            ull ap[4] = { aa0.x, aa0.y, aa1.x, aa1.y };
            ull bp[8] = { bcast2(bb0.x), bcast2(bb0.y), bcast2(bb0.z), bcast2(bb0.w),
                          bcast2(bb1.x), bcast2(bb1.y), bcast2(bb1.z), bcast2(bb1.w) };
            #pragma unroll
            for (int r = 0; r < 4; r++)
                #pragma unroll
                for (int c = 0; c < 8; c++)
                    fma2(acc[r][c], ap[r], bp[c]);
        }
    }

    // epilogue: bias + scatter to [B,H,S,64]
    float bias[8];
    {
        float4 bv0 = *(const float4*)&bi[n0 + tx*4];
        float4 bv1 = *(const float4*)&bi[n0 + 64 + tx*4];
        bias[0]=bv0.x; bias[1]=bv0.y; bias[2]=bv0.z; bias[3]=bv0.w;
        bias[4]=bv1.x; bias[5]=bv1.y; bias[6]=bv1.z; bias[7]=bv1.w;
    }
    #pragma unroll
    for (int r = 0; r < 4; r++) {
        const int m_lo = m0 + ty*8 + r*2;
        const int m_hi = m_lo + 1;
        #pragma unroll
        for (int g = 0; g < 2; g++) {
            float2 u0 = unpk(acc[r][g*4+0]);
            float2 u1 = unpk(acc[r][g*4+1]);
            float2 u2 = unpk(acc[r][g*4+2]);
            float2 u3 = unpk(acc[r][g*4+3]);
            float4 vlo = make_float4(u0.x + bias[g*4+0], u1.x + bias[g*4+1],
                                     u2.x + bias[g*4+2], u3.x + bias[g*4+3]);
            float4 vhi = make_float4(u0.y + bias[g*4+0], u1.y + bias[g*4+1],
                                     u2.y + bias[g*4+2], u3.y + bias[g*4+3]);
            const int n  = n0 + g*64 + tx*4;
            const int hh = n >> 6;
            const int dd = n & 63;
            const int b_lo = m_lo >> 11, s_lo = m_lo & 2047;
            const int b_hi = m_hi >> 11, s_hi = m_hi & 2047;
            size_t o_lo = ((size_t)(b_lo*16 + hh) * 2048 + s_lo) * 64 + dd;
            size_t o_hi = ((size_t)(b_hi*16 + hh) * 2048 + s_hi) * 64 + dd;
            *(float4*)&Out[o_lo] = vlo;
            *(float4*)&Out[o_hi] = vhi;
        }
    }
}

// =====================================================================
// Kernel 2: flash attention, fp32, online softmax.
// One CTA per (b,h) x 64-row Q tile.  KV tile = 32.  256 threads.
// Scores micro: 2 rows x 4 cols; PV micro: 2 rows x 8 d-cols (4 pairs).
// =====================================================================
__global__ void __launch_bounds__(256) attn_kernel(
    const float* __restrict__ mask, float* __restrict__ out)
{
    __shared__ float Qt[64][68];  // [d][i]   17.4 KB
    __shared__ float Kt[64][36];  // [d][j]    9.2 KB
    __shared__ float Vs[32][68];  // [j][dd]   8.7 KB
    __shared__ float Pt[32][68];  // [j][i]    8.7 KB   (total 44.0 KB)

    const int tid = threadIdx.x;
    const int tx  = tid & 7;      // 0..7  : score cols tx*4.. / V cols tx*8..
    const int ty  = tid >> 3;     // 0..31 : rows ty*2, ty*2+1
    const int q0  = blockIdx.x * 64;
    const int bh  = blockIdx.y;
    const int b   = bh >> 4;
    const int h   = bh & 15;

    const size_t hoff = (size_t)bh * 2048 * 64;
    const float* Qp = g_Q + hoff;
    const float* Kp = g_K + hoff;
    const float* Vp = g_V + hoff;
    const float* mrow = mask + b * 2048;

    // load Q tile transposed (d-major)
    #pragma unroll
    for (int it = 0; it < 4; it++) {
        int lin = tid + it * 256;        // 0..1023 float4s
        int i = lin >> 4;
        int d = (lin & 15) * 4;
        float4 v = *(const float4*)&Qp[(size_t)(q0 + i) * 64 + d];
        Qt[d+0][i] = v.x; Qt[d+1][i] = v.y; Qt[d+2][i] = v.z; Qt[d+3][i] = v.w;
    }

    float mo0 = -1e30f, mo1 = -1e30f;
    float l0 = 0.f, l1 = 0.f;
    ull O[2][4];
    #pragma unroll
    for (int r = 0; r < 2; r++)
        #pragma unroll
        for (int c = 0; c < 4; c++) O[r][c] = 0ULL;

    const int lj0 = tid >> 4;            // 0..15
    const int lj1 = lj0 + 16;
    const int ld  = (tid & 15) * 4;

    for (int t = 0; t < 64; t++) {
        const int k0 = t * 32;
        // prefetch K/V (register stage overlaps previous PV)
        float4 kr0 = *(const float4*)&Kp[(size_t)(k0 + lj0) * 64 + ld];
        float4 kr1 = *(const float4*)&Kp[(size_t)(k0 + lj1) * 64 + ld];
        float4 vr0 = *(const float4*)&Vp[(size_t)(k0 + lj0) * 64 + ld];
        float4 vr1 = *(const float4*)&Vp[(size_t)(k0 + lj1) * 64 + ld];
        float4 mk  = *(const float4*)&mrow[k0 + tx*4];
        __syncthreads();   // previous PV finished reading Vs/Pt
        Kt[ld+0][lj0]=kr0.x; Kt[ld+1][lj0]=kr0.y; Kt[ld+2][lj0]=kr0.z; Kt[ld+3][lj0]=kr0.w;
        Kt[ld+0][lj1]=kr1.x; Kt[ld+1][lj1]=kr1.y; Kt[ld+2][lj1]=kr1.z; Kt[ld+3][lj1]=kr1.w;
        *(float4*)&Vs[lj0][ld] = vr0;
        *(float4*)&Vs[lj1][ld] = vr1;
        __syncthreads();

        // ---- scores: S[i][j] = sum_d Q[i][d] K[j][d] ----
        ull sa[2][2] = {{0ULL,0ULL},{0ULL,0ULL}};
        #pragma unroll 16
        for (int d = 0; d < 64; d++) {
            float2 q2 = *(const float2*)&Qt[d][ty*2];
            ulonglong2 k2 = *(const ulonglong2*)&Kt[d][tx*4];
            ull a0 = bcast2(q2.x), a1 = bcast2(q2.y);
            fma2(sa[0][0], a0, k2.x); fma2(sa[0][1], a0, k2.y);
            fma2(sa[1][0], a1, k2.x); fma2(sa[1][1], a1, k2.y);
        }
        float s0[4], s1[4];
        { float2 u;
          u = unpk(sa[0][0]); s0[0]=u.x; s0[1]=u.y;
          u = unpk(sa[0][1]); s0[2]=u.x; s0[3]=u.y;
          u = unpk(sa[1][0]); s1[0]=u.x; s1[1]=u.y;
          u = unpk(sa[1][1]); s1[2]=u.x; s1[3]=u.y; }
        const float SC = 0.125f;
        s0[0]=fmaf(s0[0],SC,mk.x); s0[1]=fmaf(s0[1],SC,mk.y);
        s0[2]=fmaf(s0[2],SC,mk.z); s0[3]=fmaf(s0[3],SC,mk.w);
        s1[0]=fmaf(s1[0],SC,mk.x); s1[1]=fmaf(s1[1],SC,mk.y);
        s1[2]=fmaf(s1[2],SC,mk.z); s1[3]=fmaf(s1[3],SC,mk.w);

        // ---- online softmax (row reduce across the 8 tx lanes) ----
        float mr0 = fmaxf(fmaxf(s0[0],s0[1]), fmaxf(s0[2],s0[3]));
        float mr1 = fmaxf(fmaxf(s1[0],s1[1]), fmaxf(s1[2],s1[3]));
        #pragma unroll
        for (int o = 1; o < 8; o <<= 1) {
            mr0 = fmaxf(mr0, __shfl_xor_sync(0xffffffffu, mr0, o));
            mr1 = fmaxf(mr1, __shfl_xor_sync(0xffffffffu, mr1, o));
        }
        float mn0 = fmaxf(mo0, mr0), mn1 = fmaxf(mo1, mr1);
        float p0[4], p1[4];
        #pragma unroll
        for (int c = 0; c < 4; c++) {
            p0[c] = __expf(s0[c] - mn0);
            p1[c] = __expf(s1[c] - mn1);
        }
        float rs0 = (p0[0]+p0[1]) + (p0[2]+p0[3]);
        float rs1 = (p1[0]+p1[1]) + (p1[2]+p1[3]);
        #pragma unroll
        for (int o = 1; o < 8; o <<= 1) {
            rs0 += __shfl_xor_sync(0xffffffffu, rs0, o);
            rs1 += __shfl_xor_sync(0xffffffffu, rs1, o);
        }
        float al0 = __expf(mo0 - mn0), al1 = __expf(mo1 - mn1);
        l0 = l0 * al0 + rs0;
        l1 = l1 * al1 + rs1;
        mo0 = mn0; mo1 = mn1;
        { ull A0 = bcast2(al0), A1 = bcast2(al1);
          mul2(O[0][0],A0); mul2(O[0][1],A0); mul2(O[0][2],A0); mul2(O[0][3],A0);
          mul2(O[1][0],A1); mul2(O[1][1],A1); mul2(O[1][2],A1); mul2(O[1][3],A1); }

        // stage P transposed for the PV GEMM
        Pt[tx*4+0][ty*2+0]=p0[0]; Pt[tx*4+1][ty*2+0]=p0[1];
        Pt[tx*4+2][ty*2+0]=p0[2]; Pt[tx*4+3][ty*2+0]=p0[3];
        Pt[tx*4+0][ty*2+1]=p1[0]; Pt[tx*4+1][ty*2+1]=p1[1];
        Pt[tx*4+2][ty*2+1]=p1[2]; Pt[tx*4+3][ty*2+1]=p1[3];
        __syncthreads();

        // ---- PV: O[i][dd] += P[i][j] V[j][dd] ----
        #pragma unroll 8
        for (int j = 0; j < 32; j++) {
            float2 p2 = *(const float2*)&Pt[j][ty*2];
            ulonglong2 v0 = *(const ulonglong2*)&Vs[j][tx*8];
            ulonglong2 v1 = *(const ulonglong2*)&Vs[j][tx*8 + 4];
            ull a0 = bcast2(p2.x), a1 = bcast2(p2.y);
            fma2(O[0][0], a0, v0.x); fma2(O[0][1], a0, v0.y);
            fma2(O[0][2], a0, v1.x); fma2(O[0][3], a0, v1.y);
            fma2(O[1][0], a1, v0.x); fma2(O[1][1], a1, v0.y);
            fma2(O[1][2], a1, v1.x); fma2(O[1][3], a1, v1.y);
        }
    }

    // ---- epilogue: normalize, write [B,S,1024] ----
    const float inv0 = 1.0f / l0;
    const float inv1 = 1.0f / l1;
    float2 a0 = unpk(O[0][0]), a1 = unpk(O[0][1]), a2 = unpk(O[0][2]), a3 = unpk(O[0][3]);
    float2 c0 = unpk(O[1][0]), c1 = unpk(O[1][1]), c2 = unpk(O[1][2]), c3 = unpk(O[1][3]);
    const int s = q0 + ty*2;
    float* dst0 = out + ((size_t)(b*2048 + s)) * 1024 + h*64 + tx*8;
    float* dst1 = dst0 + 1024;
    *(float4*)(dst0)     = make_float4(a0.x*inv0, a0.y*inv0, a1.x*inv0, a1.y*inv0);
    *(float4*)(dst0 + 4) = make_float4(a2.x*inv0, a2.y*inv0, a3.x*inv0, a3.y*inv0);
    *(float4*)(dst1)     = make_float4(c0.x*inv1, c0.y*inv1, c1.x*inv1, c1.y*inv1);
    *(float4*)(dst1 + 4) = make_float4(c2.x*inv1, c2.y*inv1, c3.x*inv1, c3.y*inv1);
}

// =====================================================================
extern "C" void kernel_launch(void* const* d_in, const int* in_sizes, int n_in,
                              void* d_out, int out_size)
{
    const float* X    = (const float*)d_in[0];
    const float* mask = (const float*)d_in[1];
    const float* Wq   = (const float*)d_in[2];
    const float* bq   = (const float*)d_in[3];
    const float* Wk   = (const float*)d_in[4];
    const float* bk   = (const float*)d_in[5];
    const float* Wv   = (const float*)d_in[6];
    const float* bv   = (const float*)d_in[7];
    float* out = (float*)d_out;

    qkv_kernel<<<dim3(64, 8, 3), 256>>>(X, Wq, bq, Wk, bk, Wv, bv);
    attn_kernel<<<dim3(32, 64), 256>>>(mask, out);
}

// round 5
// speedup vs baseline: 1.5675x; 1.5675x over previous
#include <cuda_runtime.h>

typedef unsigned long long ull;

// ---------------- f32x2 packed helpers (Blackwell FFMA2 path) ----------------
__device__ __forceinline__ ull bcast2(float x) {
    ull d; unsigned r = __float_as_uint(x);
    asm("mov.b64 %0, {%1, %1};" : "=l"(d) : "r"(r));
    return d;
}
__device__ __forceinline__ void fma2(ull& acc, ull a, ull b) {
    asm("fma.rn.f32x2 %0, %1, %2, %0;" : "+l"(acc) : "l"(a), "l"(b));
}
__device__ __forceinline__ void mul2(ull& d, ull a) {
    asm("mul.rn.f32x2 %0, %0, %1;" : "+l"(d) : "l"(a));
}
__device__ __forceinline__ float2 unpk(ull v) {
    unsigned lo, hi;
    asm("mov.b64 {%0, %1}, %2;" : "=r"(lo), "=r"(hi) : "l"(v));
    return make_float2(__uint_as_float(lo), __uint_as_float(hi));
}

// ---------------- scratch: Q/K/V in [B,H,S,64] layout ----------------
__device__ float g_Q[64u * 2048u * 64u];
__device__ float g_K[64u * 2048u * 64u];
__device__ float g_V[64u * 2048u * 64u];

// =====================================================================
// Kernel 1: QKV projection (unchanged from passing round).
// =====================================================================
__global__ void __launch_bounds__(256) qkv_kernel(
    const float* __restrict__ X,
    const float* __restrict__ Wq, const float* __restrict__ bq,
    const float* __restrict__ Wk, const float* __restrict__ bk,
    const float* __restrict__ Wv, const float* __restrict__ bv)
{
    __shared__ float As[16][132];
    __shared__ float Bs[16][132];

    const int tid = threadIdx.x;
    const int tx  = tid & 15;
    const int ty  = tid >> 4;
    const int m0  = blockIdx.x * 128;
    const int n0  = blockIdx.y * 128;
    const int z   = blockIdx.z;

    const float* W   = (z == 0) ? Wq : (z == 1) ? Wk : Wv;
    const float* bi  = (z == 0) ? bq : (z == 1) ? bk : bv;
    float*       Out = (z == 0) ? g_Q : (z == 1) ? g_K : g_V;

    const int lrow = tid >> 2;
    const int lcol = (tid & 3) * 4;

    ull acc[4][8];
    #pragma unroll
    for (int r = 0; r < 4; r++)
        #pragma unroll
        for (int c = 0; c < 8; c++) acc[r][c] = 0ULL;

    const float* xA0 = X + (size_t)(m0 + lrow) * 1024 + lcol;
    const float* xA1 = xA0 + (size_t)64 * 1024;
    const float* xB0 = W + (size_t)(n0 + lrow) * 1024 + lcol;
    const float* xB1 = xB0 + (size_t)64 * 1024;

    for (int k0 = 0; k0 < 1024; k0 += 16) {
        float4 a0 = *(const float4*)(xA0 + k0);
        float4 a1 = *(const float4*)(xA1 + k0);
        float4 b0 = *(const float4*)(xB0 + k0);
        float4 b1 = *(const float4*)(xB1 + k0);
        __syncthreads();
        As[lcol+0][lrow] = a0.x; As[lcol+1][lrow] = a0.y;
        As[lcol+2][lrow] = a0.z; As[lcol+3][lrow] = a0.w;
        As[lcol+0][lrow+64] = a1.x; As[lcol+1][lrow+64] = a1.y;
        As[lcol+2][lrow+64] = a1.z; As[lcol+3][lrow+64] = a1.w;
        Bs[lcol+0][lrow] = b0.x; Bs[lcol+1][lrow] = b0.y;
        Bs[lcol+2][lrow] = b0.z; Bs[lcol+3][lrow] = b0.w;
        Bs[lcol+0][lrow+64] = b1.x; Bs[lcol+1][lrow+64] = b1.y;
        Bs[lcol+2][lrow+64] = b1.z; Bs[lcol+3][lrow+64] = b1.w;
        __syncthreads();

        #pragma unroll
        for (int k = 0; k < 16; k++) {
            ulonglong2 aa0 = *(const ulonglong2*)&As[k][ty*8];
            ulonglong2 aa1 = *(const ulonglong2*)&As[k][ty*8 + 4];
            float4 bb0 = *(const float4*)&Bs[k][tx*4];
            float4 bb1 = *(const float4*)&Bs[k][64 + tx*4];
            ull ap[4] = { aa0.x, aa0.y, aa1.x, aa1.y };
            ull bp[8] = { bcast2(bb0.x), bcast2(bb0.y), bcast2(bb0.z), bcast2(bb0.w),
                          bcast2(bb1.x), bcast2(bb1.y), bcast2(bb1.z), bcast2(bb1.w) };
            #pragma unroll
            for (int r = 0; r < 4; r++)
                #pragma unroll
                for (int c = 0; c < 8; c++)
                    fma2(acc[r][c], ap[r], bp[c]);
        }
    }

    float bias[8];
    {
        float4 bv0 = *(const float4*)&bi[n0 + tx*4];
        float4 bv1 = *(const float4*)&bi[n0 + 64 + tx*4];
        bias[0]=bv0.x; bias[1]=bv0.y; bias[2]=bv0.z; bias[3]=bv0.w;
        bias[4]=bv1.x; bias[5]=bv1.y; bias[6]=bv1.z; bias[7]=bv1.w;
    }
    #pragma unroll
    for (int r = 0; r < 4; r++) {
        const int m_lo = m0 + ty*8 + r*2;
        const int m_hi = m_lo + 1;
        #pragma unroll
        for (int g = 0; g < 2; g++) {
            float2 u0 = unpk(acc[r][g*4+0]);
            float2 u1 = unpk(acc[r][g*4+1]);
            float2 u2 = unpk(acc[r][g*4+2]);
            float2 u3 = unpk(acc[r][g*4+3]);
            float4 vlo = make_float4(u0.x + bias[g*4+0], u1.x + bias[g*4+1],
                                     u2.x + bias[g*4+2], u3.x + bias[g*4+3]);
            float4 vhi = make_float4(u0.y + bias[g*4+0], u1.y + bias[g*4+1],
                                     u2.y + bias[g*4+2], u3.y + bias[g*4+3]);
            const int n  = n0 + g*64 + tx*4;
            const int hh = n >> 6;
            const int dd = n & 63;
            const int b_lo = m_lo >> 11, s_lo = m_lo & 2047;
            const int b_hi = m_hi >> 11, s_hi = m_hi & 2047;
            size_t o_lo = ((size_t)(b_lo*16 + hh) * 2048 + s_lo) * 64 + dd;
            size_t o_hi = ((size_t)(b_hi*16 + hh) * 2048 + s_hi) * 64 + dd;
            *(float4*)&Out[o_lo] = vlo;
            *(float4*)&Out[o_hi] = vhi;
        }
    }
}

// =====================================================================
// Kernel 2: flash attention v2 — 8x8 microtiles in both GEMMs.
// Q tile 128, KV tile 128, 256 threads, dynamic smem 169.5 KB.
// Score: rg=tid>>4 (rows rg*8, as 4 f32x2 row-pairs), cg=tid&15 (cols cg*8).
// PV:    rgp=(tid>>3)&15 (rows rgp*8), dg=tid&7 (dd dg*8), jh=tid>>7 (j half).
// =====================================================================

// smem layout (float offsets)
#define QT_OFF 0            // [64][132]  (d-major Q)
#define KT_OFF 8448         // [64][132]  (d-major K)
#define VS_OFF 16896        // [128][68]  (j-major V)
#define PT_OFF 25600        // [128][129] (j-major P, odd stride -> 4-way write max)
#define AL_OFF 42112        // row_alpha[128]
#define LS_OFF 42240        // row_l[128]
#define SM_FLOATS 42368     // 169472 bytes

__global__ void __launch_bounds__(256, 1) attn_kernel(
    const float* __restrict__ mask, float* __restrict__ out)
{
    extern __shared__ float sm[];
    float* Qt = sm + QT_OFF;
    float* Kt = sm + KT_OFF;
    float* Vs = sm + VS_OFF;
    float* Pt = sm + PT_OFF;
    float* row_alpha = sm + AL_OFF;
    float* row_l     = sm + LS_OFF;

    const int tid = threadIdx.x;
    // score mapping
    const int cg = tid & 15;          // cols cg*8 .. cg*8+7
    const int rg = tid >> 4;          // rows rg*8 .. rg*8+7 (4 pairs)
    // PV mapping
    const int dg  = tid & 7;          // dd dg*8 .. +7
    const int rgp = (tid >> 3) & 15;  // rows rgp*8 .. +7
    const int jh  = tid >> 7;         // j half: jh*64 .. +63

    const int q0 = blockIdx.x * 128;
    const int bh = blockIdx.y;
    const int b  = bh >> 4;
    const int h  = bh & 15;

    const size_t hoff = (size_t)bh * 2048 * 64;
    const float* Qp = g_Q + hoff;
    const float* Kp = g_K + hoff;
    const float* Vp = g_V + hoff;
    const float* mrow = mask + b * 2048;

    // ---- load Q tile transposed: Qt[d][i] ----
    #pragma unroll
    for (int it = 0; it < 8; it++) {
        int lin = it * 256 + tid;       // 2048 float4s
        int i  = lin & 127;
        int d4 = lin >> 7;              // 0..15
        float4 v = *(const float4*)&Qp[(size_t)(q0 + i) * 64 + d4 * 4];
        Qt[(d4*4+0)*132 + i] = v.x;
        Qt[(d4*4+1)*132 + i] = v.y;
        Qt[(d4*4+2)*132 + i] = v.z;
        Qt[(d4*4+3)*132 + i] = v.w;
    }

    float mo[8], lsum[8];
    #pragma unroll
    for (int r = 0; r < 8; r++) { mo[r] = -1e30f; lsum[r] = 0.f; }

    ull O[8][4];
    #pragma unroll
    for (int r = 0; r < 8; r++)
        #pragma unroll
        for (int dp = 0; dp < 4; dp++) O[r][dp] = 0ULL;

    for (int t = 0; t < 16; t++) {
        const int k0 = t * 128;

        __syncthreads();   // PV of t-1 done reading Kt/Vs/Pt

        // ---- load K tile transposed: Kt[d][j] ----
        #pragma unroll
        for (int it = 0; it < 8; it++) {
            int lin = it * 256 + tid;
            int j  = lin & 127;
            int d4 = lin >> 7;
            float4 v = *(const float4*)&Kp[(size_t)(k0 + j) * 64 + d4 * 4];
            Kt[(d4*4+0)*132 + j] = v.x;
            Kt[(d4*4+1)*132 + j] = v.y;
            Kt[(d4*4+2)*132 + j] = v.z;
            Kt[(d4*4+3)*132 + j] = v.w;
        }
        // ---- load V tile: Vs[j][dd] ----
        #pragma unroll
        for (int it = 0; it < 8; it++) {
            int lin = it * 256 + tid;
            int d4 = lin & 15;
            int j  = lin >> 4;
            float4 v = *(const float4*)&Vp[(size_t)(k0 + j) * 64 + d4 * 4];
            *(float4*)&Vs[j * 68 + d4 * 4] = v;
        }
        // mask slice for this thread's 8 cols
        float mk[8];
        {
            float4 ma = *(const float4*)&mrow[k0 + cg*8];
            float4 mb = *(const float4*)&mrow[k0 + cg*8 + 4];
            mk[0]=ma.x; mk[1]=ma.y; mk[2]=ma.z; mk[3]=ma.w;
            mk[4]=mb.x; mk[5]=mb.y; mk[6]=mb.z; mk[7]=mb.w;
        }
        __syncthreads();

        // ---- scores: 8 rows (4 f32x2 pairs) x 8 cols ----
        ull sa[4][8];
        #pragma unroll
        for (int rp = 0; rp < 4; rp++)
            #pragma unroll
            for (int c = 0; c < 8; c++) sa[rp][c] = 0ULL;

        #pragma unroll 8
        for (int d = 0; d < 64; d++) {
            ulonglong2 qa = *(const ulonglong2*)&Qt[d*132 + rg*8];
            ulonglong2 qb = *(const ulonglong2*)&Qt[d*132 + rg*8 + 4];
            float4 ka = *(const float4*)&Kt[d*132 + cg*8];
            float4 kb = *(const float4*)&Kt[d*132 + cg*8 + 4];
            ull ap[4] = { qa.x, qa.y, qb.x, qb.y };
            ull bp[8] = { bcast2(ka.x), bcast2(ka.y), bcast2(ka.z), bcast2(ka.w),
                          bcast2(kb.x), bcast2(kb.y), bcast2(kb.z), bcast2(kb.w) };
            #pragma unroll
            for (int rp = 0; rp < 4; rp++)
                #pragma unroll
                for (int c = 0; c < 8; c++)
                    fma2(sa[rp][c], ap[rp], bp[c]);
        }

        // ---- softmax per row-pair; stage P^T; publish alpha ----
        const float SC = 0.125f;
        #pragma unroll
        for (int rp = 0; rp < 4; rp++) {
            float s0[8], s1[8];
            #pragma unroll
            for (int c = 0; c < 8; c++) {
                float2 u = unpk(sa[rp][c]);
                s0[c] = fmaf(u.x, SC, mk[c]);
                s1[c] = fmaf(u.y, SC, mk[c]);
            }
            float m0 = s0[0], m1 = s1[0];
            #pragma unroll
            for (int c = 1; c < 8; c++) { m0 = fmaxf(m0, s0[c]); m1 = fmaxf(m1, s1[c]); }
            #pragma unroll
            for (int o = 1; o < 16; o <<= 1) {
                m0 = fmaxf(m0, __shfl_xor_sync(0xffffffffu, m0, o));
                m1 = fmaxf(m1, __shfl_xor_sync(0xffffffffu, m1, o));
            }
            float mn0 = fmaxf(mo[2*rp],   m0);
            float mn1 = fmaxf(mo[2*rp+1], m1);
            float p0[8], p1[8];
            float rs0 = 0.f, rs1 = 0.f;
            #pragma unroll
            for (int c = 0; c < 8; c++) {
                p0[c] = __expf(s0[c] - mn0); rs0 += p0[c];
                p1[c] = __expf(s1[c] - mn1); rs1 += p1[c];
            }
            #pragma unroll
            for (int o = 1; o < 16; o <<= 1) {
                rs0 += __shfl_xor_sync(0xffffffffu, rs0, o);
                rs1 += __shfl_xor_sync(0xffffffffu, rs1, o);
            }
            float al0 = __expf(mo[2*rp]   - mn0);
            float al1 = __expf(mo[2*rp+1] - mn1);
            lsum[2*rp]   = lsum[2*rp]   * al0 + rs0;
            lsum[2*rp+1] = lsum[2*rp+1] * al1 + rs1;
            mo[2*rp] = mn0; mo[2*rp+1] = mn1;
            if (cg == 0) {
                row_alpha[rg*8 + 2*rp]     = al0;
                row_alpha[rg*8 + 2*rp + 1] = al1;
            }
            #pragma unroll
            for (int c = 0; c < 8; c++) {
                Pt[(cg*8 + c)*129 + rg*8 + 2*rp]     = p0[c];
                Pt[(cg*8 + c)*129 + rg*8 + 2*rp + 1] = p1[c];
            }
        }
        __syncthreads();   // Pt + row_alpha visible

        // ---- PV: rescale O by alpha, accumulate this tile's half-j range ----
        {
            #pragma unroll
            for (int r = 0; r < 8; r++) {
                ull alp = bcast2(row_alpha[rgp*8 + r]);
                #pragma unroll
                for (int dp = 0; dp < 4; dp++) mul2(O[r][dp], alp);
            }
            const int jbase = jh * 64;
            #pragma unroll 4
            for (int jj = 0; jj < 64; jj++) {
                const int j = jbase + jj;
                ulonglong2 v0 = *(const ulonglong2*)&Vs[j*68 + dg*8];
                ulonglong2 v1 = *(const ulonglong2*)&Vs[j*68 + dg*8 + 4];
                ull vb[4] = { v0.x, v0.y, v1.x, v1.y };
                const float* prow = &Pt[j*129 + rgp*8];
                #pragma unroll
                for (int r = 0; r < 8; r++) {
                    ull pa = bcast2(prow[r]);
                    fma2(O[r][0], pa, vb[0]);
                    fma2(O[r][1], pa, vb[1]);
                    fma2(O[r][2], pa, vb[2]);
                    fma2(O[r][3], pa, vb[3]);
                }
            }
        }
    }

    // ---- epilogue ----
    if (cg == 0) {
        #pragma unroll
        for (int r = 0; r < 8; r++) row_l[rg*8 + r] = lsum[r];
    }
    __syncthreads();

    ull* Obuf = (ull*)(sm + PT_OFF);   // reuse Pt: 128 threads x 32 ull = 32 KB
    if (jh == 1) {
        int base = (tid - 128) * 32;
        #pragma unroll
        for (int r = 0; r < 8; r++)
            #pragma unroll
            for (int dp = 0; dp < 4; dp++)
                Obuf[base + r*4 + dp] = O[r][dp];
    }
    __syncthreads();

    if (jh == 0) {
        int base = tid * 32;
        #pragma unroll
        for (int r = 0; r < 8; r++) {
            const int i = rgp*8 + r;
            float inv = 1.0f / row_l[i];
            float2 x0 = unpk(O[r][0]), x1 = unpk(O[r][1]);
            float2 x2 = unpk(O[r][2]), x3 = unpk(O[r][3]);
            float2 y0 = unpk(Obuf[base + r*4 + 0]);
            float2 y1 = unpk(Obuf[base + r*4 + 1]);
            float2 y2 = unpk(Obuf[base + r*4 + 2]);
            float2 y3 = unpk(Obuf[base + r*4 + 3]);
            float4 o0 = make_float4((x0.x+y0.x)*inv, (x0.y+y0.y)*inv,
                                    (x1.x+y1.x)*inv, (x1.y+y1.y)*inv);
            float4 o1 = make_float4((x2.x+y2.x)*inv, (x2.y+y2.y)*inv,
                                    (x3.x+y3.x)*inv, (x3.y+y3.y)*inv);
            float* dst = out + ((size_t)(b*2048 + q0 + i)) * 1024 + h*64 + dg*8;
            *(float4*)dst       = o0;
            *(float4*)(dst + 4) = o1;
        }
    }
}

// =====================================================================
extern "C" void kernel_launch(void* const* d_in, const int* in_sizes, int n_in,
                              void* d_out, int out_size)
{
    const float* X    = (const float*)d_in[0];
    const float* mask = (const float*)d_in[1];
    const float* Wq   = (const float*)d_in[2];
    const float* bq   = (const float*)d_in[3];
    const float* Wk   = (const float*)d_in[4];
    const float* bk   = (const float*)d_in[5];
    const float* Wv   = (const float*)d_in[6];
    const float* bv   = (const float*)d_in[7];
    float* out = (float*)d_out;

    cudaFuncSetAttribute(attn_kernel,
                         cudaFuncAttributeMaxDynamicSharedMemorySize,
                         SM_FLOATS * 4);

    qkv_kernel<<<dim3(64, 8, 3), 256>>>(X, Wq, bq, Wk, bk, Wv, bv);
    attn_kernel<<<dim3(16, 64), 256, SM_FLOATS * 4>>>(mask, out);
}